// round 13
// baseline (speedup 1.0000x reference)
#include <cuda_runtime.h>
#include <cuda_fp16.h>
#include <cstdint>

// ---------------- problem constants ----------------
#define BB   32
#define CI_  128
#define CO_  128
#define HH   56
#define WW   56
#define HW   3136          // 56*56
#define PADW 58            // padded x
#define PADH 60            // padded y (extra rows for tail-tile garbage reads)

#define MTILE 128          // flattened pixels per CTA
#define NTILES 25          // ceil(3136/128) (tail half-masked)

#define AROWS 307          // exact halo bound (max smem row index 306)
#define ABYTES (AROWS * 128)        // 39296  (64 fp16 per row)
#define BBYTES (CO_ * 128)          // 16384 per buffer (128 co x 64 fp16)
#define NBUF   4
#define SMEM_CONV (ABYTES + NBUF * BBYTES)   // 104832 -> 2 CTAs/SM

#define PREPW_BLOCKS  2048          // 2 co per block
#define INTRANS_BLOCKS (98 * 4 * 32)

// ---------------- scratch (device globals; fp16) ----------------
__device__ __half g_W2h [(size_t)BB * 9 * CO_ * CI_];       // [b][tap][co][ci]
__device__ __half g_padh[(size_t)BB * PADH * PADW * CI_];   // [b][y][x][ci]

// ---------------- helpers ----------------
__device__ __forceinline__ uint32_t smem_to_u32(const void* p) {
    uint32_t a;
    asm("{ .reg .u64 t; cvta.to.shared.u64 t, %1; cvt.u32.u64 %0, t; }" : "=r"(a) : "l"(p));
    return a;
}
__device__ __forceinline__ void ldsm_x4(uint32_t* r, uint32_t addr) {
    asm volatile("ldmatrix.sync.aligned.m8n8.x4.shared.b16 {%0,%1,%2,%3}, [%4];"
        : "=r"(r[0]), "=r"(r[1]), "=r"(r[2]), "=r"(r[3]) : "r"(addr));
}
__device__ __forceinline__ void mma_fp16(float* c, const uint32_t* a, const uint32_t* b) {
    asm volatile("mma.sync.aligned.m16n8k16.row.col.f32.f16.f16.f32 "
        "{%0,%1,%2,%3}, {%4,%5,%6,%7}, {%8,%9}, {%0,%1,%2,%3};"
        : "+f"(c[0]), "+f"(c[1]), "+f"(c[2]), "+f"(c[3])
        : "r"(a[0]), "r"(a[1]), "r"(a[2]), "r"(a[3]), "r"(b[0]), "r"(b[1]));
}
__device__ __forceinline__ void cp16(uint32_t dst, const void* src) {
    asm volatile("cp.async.cg.shared.global [%0], [%1], 16;" :: "r"(dst), "l"(src));
}
#define CP_COMMIT() asm volatile("cp.async.commit_group;" ::: "memory")
#define CP_WAIT0()  asm volatile("cp.async.wait_group 0;" ::: "memory")

// ---------------------------------------------------------------------------
// fused prep: block < PREPW_BLOCKS   -> weight reparam+transpose (2 co/block)
//             block >= PREPW_BLOCKS  -> input NCHW -> padded NHWC fp16
//                                       (+ border zeroing in first 688 blocks)
// ---------------------------------------------------------------------------
__global__ __launch_bounds__(256) void prep_all(const float* __restrict__ in,
                                                const float* __restrict__ eps,
                                                const float* __restrict__ psi,
                                                const float* __restrict__ mu) {
    __shared__ float t[32][33];
    int blk = blockIdx.x;
    int tid = threadIdx.x;

    if (blk < PREPW_BLOCKS) {
        int b  = blk >> 6;
        int co = ((blk & 63) << 1) + (tid >> 7);
        int ci = tid & 127;
        const float* e = eps + ((size_t)(b * CO_ + co) * CI_ + ci) * 9;
        const float* p = psi + ((size_t)co * CI_ + ci) * 9;
        const float* m = mu  + ((size_t)co * CI_ + ci) * 9;
        float v[9];
#pragma unroll
        for (int k = 0; k < 9; k++)
            v[k] = fmaf(e[k], __expf(p[k]), m[k]);
#pragma unroll
        for (int k = 0; k < 9; k++)
            g_W2h[((size_t)(b * 9 + k) * CO_ + co) * CI_ + ci] = __float2half_rn(v[k]);
        return;
    }

    int blk2 = blk - PREPW_BLOCKS;
    if (blk2 < 688) {
        int gi = blk2 * 256 + tid;
        int bz = gi / (344 * 16);
        int r  = gi % (344 * 16);
        int pi = r >> 4, f = r & 15;
        int y, x;
        if (pi < 58)       { y = 0;  x = pi; }
        else if (pi < 116) { y = 57; x = pi - 58; }
        else if (pi < 174) { y = 58; x = pi - 116; }
        else if (pi < 232) { y = 59; x = pi - 174; }
        else if (pi < 288) { y = pi - 232 + 1; x = 0; }
        else               { y = pi - 288 + 1; x = 57; }
        ((float4*)g_padh)[(((size_t)bz * PADH + y) * PADW + x) * 16 + f] =
            make_float4(0.f, 0.f, 0.f, 0.f);
    }

    int bx = blk2 % 98;
    int rem = blk2 / 98;
    int by = rem & 3;
    int bz = rem >> 2;
    int tx = tid & 31, ty = tid >> 5;
    int b = bz, hw0 = bx * 32, ci0 = by * 32;

    const float* ib = in + (size_t)b * CI_ * HW;
#pragma unroll
    for (int j = 0; j < 32; j += 8)
        t[ty + j][tx] = ib[(size_t)(ci0 + ty + j) * HW + hw0 + tx];
    __syncthreads();
#pragma unroll
    for (int j = 0; j < 32; j += 8) {
        int hw = hw0 + ty + j;
        int y = hw / WW, x = hw - y * WW;
        g_padh[(((size_t)b * PADH + y + 1) * PADW + (x + 1)) * CI_ + ci0 + tx] =
            __float2half_rn(t[tx][ty + j]);
    }
}

// ---------------------------------------------------------------------------
// conv: implicit GEMM, mma.sync fp16 (m16n8k16), cp.async staging.
// CTA = 128 flattened pixels x 128 co, warp grid 2(M) x 4(N).
// computeTap pipelined: B frags double-buffered across kk (prefetch kk+2
// AFTER all 16 mmas of kk — fixes the R12 aliasing race), A frags
// ping-ponged across mf. grid (25, 32), block 256, 2 CTAs/SM.
// ---------------------------------------------------------------------------
__global__ __launch_bounds__(256, 2) void conv_mma(float* __restrict__ out) {
    extern __shared__ __align__(128) char smem[];
    uint32_t As_u = smem_to_u32(smem);
    uint32_t Bs_u = As_u + ABYTES;

    int tid = threadIdx.x, lid = tid & 31, wid = tid >> 5;
    int tile = blockIdx.x, b = blockIdx.y;
    int m_w = wid >> 2;
    int n_w = wid & 3;

    int p0   = tile * MTILE;
    int y_lo = p0 / WW;

    const __half* apage = g_padh + (((size_t)b * PADH + y_lo) * PADW) * CI_;
    const __half* wpage = g_W2h + (size_t)b * 9 * CO_ * CI_;

    int rA    = lid & 7;
    int add8A = ((lid >> 3) & 1) << 3;
    int jAh   = lid >> 4;
    int jBh   = (lid >> 3) & 1;
    int rowB  = n_w * 32 + (((lid >> 4) & 1) << 3) + rA;
    uint32_t b_base  = Bs_u + (uint32_t)rowB * 128;
    uint32_t xorB_sh = (uint32_t)rA << 4;

    int row_pq[4];
#pragma unroll
    for (int mf = 0; mf < 4; mf++) {
        int p  = p0 + (m_w * 4 + mf) * 16 + rA + add8A;
        int y  = p / WW;
        row_pq[mf] = (y - y_lo) * PADW + (p - y * WW);
    }

    float acc[4][4][4];
#pragma unroll
    for (int mf = 0; mf < 4; mf++)
#pragma unroll
        for (int nn = 0; nn < 4; nn++)
#pragma unroll
            for (int q = 0; q < 4; q++) acc[mf][nn][q] = 0.f;

    auto stageB = [&](int uv, int ccol) {
        const __half* wsrc = wpage + (size_t)uv * CO_ * CI_ + ccol;
        uint32_t dstb = Bs_u + (uint32_t)((uv & 3) * BBYTES);
#pragma unroll
        for (int t = 0; t < 4; t++) {
            int c = tid + t * 256;
            int co = c >> 3, j = c & 7;
            cp16(dstb + (uint32_t)(co * 128 + ((j ^ (co & 7)) << 4)),
                 wsrc + (size_t)co * CI_ + j * 8);
        }
    };
    auto ldB = [&](uint32_t* bf, uint32_t bb, int kk) {
        uint32_t koffB = (uint32_t)(kk * 32 + jBh * 16);
        ldsm_x4(bf,     bb +        (koffB ^ xorB_sh));
        ldsm_x4(bf + 4, bb + 2048 + (koffB ^ xorB_sh));
    };

    auto computeTap = [&](int uv) {
        int u = uv / 3, v = uv - u * 3;
        int du = u * PADW + v;
        uint32_t abase[4], axsh[4];
#pragma unroll
        for (int mf = 0; mf < 4; mf++) {
            int q = row_pq[mf] + du;
            abase[mf] = As_u + (uint32_t)q * 128;
            axsh[mf]  = (uint32_t)(q & 7) << 4;
        }
        uint32_t bb = b_base + (uint32_t)((uv & 3) * BBYTES);

        uint32_t bfr[2][8];
        ldB(bfr[0], bb, 0);
        ldB(bfr[1], bb, 1);
#pragma unroll
        for (int kk = 0; kk < 4; kk++) {
            uint32_t koffA = (uint32_t)(kk * 32 + jAh * 16);
            uint32_t* bf = bfr[kk & 1];
            uint32_t afA[4], afB[4];
            ldsm_x4(afA, abase[0] + (koffA ^ axsh[0]));
            ldsm_x4(afB, abase[1] + (koffA ^ axsh[1]));
            mma_fp16(acc[0][0], afA, bf);
            mma_fp16(acc[0][1], afA, bf + 2);
            mma_fp16(acc[0][2], afA, bf + 4);
            mma_fp16(acc[0][3], afA, bf + 6);
            ldsm_x4(afA, abase[2] + (koffA ^ axsh[2]));
            mma_fp16(acc[1][0], afB, bf);
            mma_fp16(acc[1][1], afB, bf + 2);
            mma_fp16(acc[1][2], afB, bf + 4);
            mma_fp16(acc[1][3], afB, bf + 6);
            ldsm_x4(afB, abase[3] + (koffA ^ axsh[3]));
            mma_fp16(acc[2][0], afA, bf);
            mma_fp16(acc[2][1], afA, bf + 2);
            mma_fp16(acc[2][2], afA, bf + 4);
            mma_fp16(acc[2][3], afA, bf + 6);
            mma_fp16(acc[3][0], afB, bf);
            mma_fp16(acc[3][1], afB, bf + 2);
            mma_fp16(acc[3][2], afB, bf + 4);
            mma_fp16(acc[3][3], afB, bf + 6);
            // prefetch B for kk+2 into this parity slot — AFTER all users of bf
            if (kk < 2) ldB(bfr[kk & 1], bb, kk + 2);
        }
    };

    for (int cc = 0; cc < 2; cc++) {
        int ccol = cc * 64;
        __syncthreads();

        // ---- stage A: 307 rows x 8 x 16B, swizzled ----
#pragma unroll
        for (int t = 0; t < 10; t++) {
            int c = tid + t * 256;
            if (t < 9 || c < AROWS * 8) {
                int q = c >> 3, j = c & 7;
                cp16(As_u + (uint32_t)(q * 128 + ((j ^ (q & 7)) << 4)),
                     apage + (size_t)q * CI_ + ccol + j * 8);
            }
        }
        stageB(0, ccol);
        stageB(1, ccol);
        CP_COMMIT();

#pragma unroll 1
        for (int w2 = 0; w2 < 9; w2 += 2) {
            CP_WAIT0();
            __syncthreads();
            if (w2 + 2 < 9) {
                stageB(w2 + 2, ccol);
                if (w2 + 3 < 9) stageB(w2 + 3, ccol);
                CP_COMMIT();
            }
#pragma unroll 1
            for (int t = 0; t < 2; t++) {
                int uv = w2 + t;
                if (uv < 9) computeTap(uv);
            }
        }
    }

    // ---- epilogue: direct NCHW stores ----
    float* ob = out + (size_t)b * CO_ * HW;
    int g = lid >> 2, tg = lid & 3;
#pragma unroll
    for (int mf = 0; mf < 4; mf++) {
#pragma unroll
        for (int h = 0; h < 2; h++) {
            int p = p0 + (m_w * 4 + mf) * 16 + g + 8 * h;
            if (p < HW) {
#pragma unroll
                for (int nn = 0; nn < 4; nn++) {
                    int col = n_w * 32 + nn * 8 + (tg << 1);
                    ob[(size_t)col * HW + p]       = acc[mf][nn][2 * h];
                    ob[(size_t)(col + 1) * HW + p] = acc[mf][nn][2 * h + 1];
                }
            }
        }
    }
}

// ---------------------------------------------------------------------------
extern "C" void kernel_launch(void* const* d_in, const int* in_sizes, int n_in,
                              void* d_out, int out_size) {
    const float* input = (const float*)d_in[0];   // [32,128,56,56]
    const float* eps   = (const float*)d_in[1];   // [32,128,128,3,3]
    const float* psi   = (const float*)d_in[2];   // [128,128,3,3]
    const float* mu    = (const float*)d_in[3];   // [128,128,3,3]
    float* out = (float*)d_out;                   // [32,128,56,56]

    prep_all<<<PREPW_BLOCKS + INTRANS_BLOCKS, 256>>>(input, eps, psi, mu);

    cudaFuncSetAttribute(conv_mma, cudaFuncAttributeMaxDynamicSharedMemorySize, SMEM_CONV);
    conv_mma<<<dim3(NTILES, BB), 256, SMEM_CONV>>>(out);
}

// round 14
// speedup vs baseline: 1.0028x; 1.0028x over previous
#include <cuda_runtime.h>
#include <cuda_fp16.h>
#include <cstdint>

// ---------------- problem constants ----------------
#define BB   32
#define CI_  128
#define CO_  128
#define HH   56
#define WW   56
#define HW   3136          // 56*56
#define PADW 58            // padded x
#define PADH 60            // padded y (extra rows for tail-tile garbage reads)

#define MTILE 128          // flattened pixels per CTA
#define NTILES 25          // ceil(3136/128) (tail half-masked)

#define AROWS 307          // exact halo bound (max smem row index 306)
#define ABYTES (AROWS * 128)        // 39296  (64 fp16 per row)
#define BBYTES (CO_ * 128)          // 16384 per buffer (128 co x 64 fp16)
#define NBUF   4
#define SMEM_CONV (ABYTES + NBUF * BBYTES)   // 104832 -> 2 CTAs/SM

#define NPREPW   2048               // weight-prep block-units (2 co each)
#define NINTRANS (98 * 4 * 32)      // 12544 transpose block-units
#define NMIX     (NPREPW * 7)       // 14336 interleaved region
#define NPREP_TOTAL (NPREPW + NINTRANS)   // 14592

// ---------------- scratch (device globals; fp16) ----------------
__device__ __half g_W2h [(size_t)BB * 9 * CO_ * CI_];       // [b][tap][co][ci]
__device__ __half g_padh[(size_t)BB * PADH * PADW * CI_];   // [b][y][x][ci]

// ---------------- helpers ----------------
__device__ __forceinline__ uint32_t smem_to_u32(const void* p) {
    uint32_t a;
    asm("{ .reg .u64 t; cvta.to.shared.u64 t, %1; cvt.u32.u64 %0, t; }" : "=r"(a) : "l"(p));
    return a;
}
__device__ __forceinline__ void ldsm_x4(uint32_t* r, uint32_t addr) {
    asm volatile("ldmatrix.sync.aligned.m8n8.x4.shared.b16 {%0,%1,%2,%3}, [%4];"
        : "=r"(r[0]), "=r"(r[1]), "=r"(r[2]), "=r"(r[3]) : "r"(addr));
}
__device__ __forceinline__ void mma_fp16(float* c, const uint32_t* a, const uint32_t* b) {
    asm volatile("mma.sync.aligned.m16n8k16.row.col.f32.f16.f16.f32 "
        "{%0,%1,%2,%3}, {%4,%5,%6,%7}, {%8,%9}, {%0,%1,%2,%3};"
        : "+f"(c[0]), "+f"(c[1]), "+f"(c[2]), "+f"(c[3])
        : "r"(a[0]), "r"(a[1]), "r"(a[2]), "r"(a[3]), "r"(b[0]), "r"(b[1]));
}
__device__ __forceinline__ void cp16(uint32_t dst, const void* src) {
    asm volatile("cp.async.cg.shared.global [%0], [%1], 16;" :: "r"(dst), "l"(src));
}
#define CP_COMMIT() asm volatile("cp.async.commit_group;" ::: "memory")
#define CP_WAIT0()  asm volatile("cp.async.wait_group 0;" ::: "memory")

// ---------------------------------------------------------------------------
// fused prep, role-INTERLEAVED so the compute-heavy weight reparam overlaps
// the BW-heavy input transpose:
//   blk in [0, NMIX):  blk%7==0 -> prepw(blk/7); else intrans(blk - blk/7 - 1)
//   blk in [NMIX, ..): intrans(blk - NPREPW)
// ---------------------------------------------------------------------------
__device__ __forceinline__ void prepw_unit(int unit, const float* __restrict__ eps,
                                           const float* __restrict__ psi,
                                           const float* __restrict__ mu, int tid) {
    int b  = unit >> 6;
    int co = ((unit & 63) << 1) + (tid >> 7);
    int ci = tid & 127;
    const float* e = eps + ((size_t)(b * CO_ + co) * CI_ + ci) * 9;
    const float* p = psi + ((size_t)co * CI_ + ci) * 9;
    const float* m = mu  + ((size_t)co * CI_ + ci) * 9;
    float v[9];
#pragma unroll
    for (int k = 0; k < 9; k++)
        v[k] = fmaf(e[k], __expf(p[k]), m[k]);
#pragma unroll
    for (int k = 0; k < 9; k++)
        g_W2h[((size_t)(b * 9 + k) * CO_ + co) * CI_ + ci] = __float2half_rn(v[k]);
}

__global__ __launch_bounds__(256) void prep_all(const float* __restrict__ in,
                                                const float* __restrict__ eps,
                                                const float* __restrict__ psi,
                                                const float* __restrict__ mu) {
    __shared__ float t[32][33];
    int blk = blockIdx.x;
    int tid = threadIdx.x;

    int iunit;
    if (blk < NMIX) {
        int q = blk / 7;
        if (blk - q * 7 == 0) {              // prepw role
            prepw_unit(q, eps, psi, mu, tid);
            return;
        }
        iunit = blk - q - 1;
    } else {
        iunit = blk - NPREPW;
    }

    // ---- border zeroing: first 688 intrans units also zero pad borders ----
    if (iunit < 688) {
        int gi = iunit * 256 + tid;
        int bz = gi / (344 * 16);
        int r  = gi % (344 * 16);
        int pi = r >> 4, f = r & 15;
        int y, x;
        if (pi < 58)       { y = 0;  x = pi; }
        else if (pi < 116) { y = 57; x = pi - 58; }
        else if (pi < 174) { y = 58; x = pi - 116; }
        else if (pi < 232) { y = 59; x = pi - 174; }
        else if (pi < 288) { y = pi - 232 + 1; x = 0; }
        else               { y = pi - 288 + 1; x = 57; }
        ((float4*)g_padh)[(((size_t)bz * PADH + y) * PADW + x) * 16 + f] =
            make_float4(0.f, 0.f, 0.f, 0.f);
    }

    // ---- input transpose: emulate grid (98, 4, 32), block (32, 8) ----
    int bx = iunit % 98;
    int rem = iunit / 98;
    int by = rem & 3;
    int bz = rem >> 2;
    int tx = tid & 31, ty = tid >> 5;
    int b = bz, hw0 = bx * 32, ci0 = by * 32;

    const float* ib = in + (size_t)b * CI_ * HW;
#pragma unroll
    for (int j = 0; j < 32; j += 8)
        t[ty + j][tx] = ib[(size_t)(ci0 + ty + j) * HW + hw0 + tx];
    __syncthreads();
#pragma unroll
    for (int j = 0; j < 32; j += 8) {
        int hw = hw0 + ty + j;
        int y = hw / WW, x = hw - y * WW;
        g_padh[(((size_t)b * PADH + y + 1) * PADW + (x + 1)) * CI_ + ci0 + tx] =
            __float2half_rn(t[tx][ty + j]);
    }
}

// ---------------------------------------------------------------------------
// conv: implicit GEMM, mma.sync fp16 (m16n8k16), cp.async staging.
// CTA = 128 flattened pixels x 128 co, warp grid 2(M) x 4(N).
// computeTap pipelined: B frags double-buffered across kk (prefetch kk+2
// after ALL users of the slot), A frags ping-ponged across mf.
// grid (25, 32), block 256, 2 CTAs/SM.   (R13 kernel — at HMMA pipe ceiling)
// ---------------------------------------------------------------------------
__global__ __launch_bounds__(256, 2) void conv_mma(float* __restrict__ out) {
    extern __shared__ __align__(128) char smem[];
    uint32_t As_u = smem_to_u32(smem);
    uint32_t Bs_u = As_u + ABYTES;

    int tid = threadIdx.x, lid = tid & 31, wid = tid >> 5;
    int tile = blockIdx.x, b = blockIdx.y;
    int m_w = wid >> 2;
    int n_w = wid & 3;

    int p0   = tile * MTILE;
    int y_lo = p0 / WW;

    const __half* apage = g_padh + (((size_t)b * PADH + y_lo) * PADW) * CI_;
    const __half* wpage = g_W2h + (size_t)b * 9 * CO_ * CI_;

    int rA    = lid & 7;
    int add8A = ((lid >> 3) & 1) << 3;
    int jAh   = lid >> 4;
    int jBh   = (lid >> 3) & 1;
    int rowB  = n_w * 32 + (((lid >> 4) & 1) << 3) + rA;
    uint32_t b_base  = Bs_u + (uint32_t)rowB * 128;
    uint32_t xorB_sh = (uint32_t)rA << 4;

    int row_pq[4];
#pragma unroll
    for (int mf = 0; mf < 4; mf++) {
        int p  = p0 + (m_w * 4 + mf) * 16 + rA + add8A;
        int y  = p / WW;
        row_pq[mf] = (y - y_lo) * PADW + (p - y * WW);
    }

    float acc[4][4][4];
#pragma unroll
    for (int mf = 0; mf < 4; mf++)
#pragma unroll
        for (int nn = 0; nn < 4; nn++)
#pragma unroll
            for (int q = 0; q < 4; q++) acc[mf][nn][q] = 0.f;

    auto stageB = [&](int uv, int ccol) {
        const __half* wsrc = wpage + (size_t)uv * CO_ * CI_ + ccol;
        uint32_t dstb = Bs_u + (uint32_t)((uv & 3) * BBYTES);
#pragma unroll
        for (int t = 0; t < 4; t++) {
            int c = tid + t * 256;
            int co = c >> 3, j = c & 7;
            cp16(dstb + (uint32_t)(co * 128 + ((j ^ (co & 7)) << 4)),
                 wsrc + (size_t)co * CI_ + j * 8);
        }
    };
    auto ldB = [&](uint32_t* bf, uint32_t bb, int kk) {
        uint32_t koffB = (uint32_t)(kk * 32 + jBh * 16);
        ldsm_x4(bf,     bb +        (koffB ^ xorB_sh));
        ldsm_x4(bf + 4, bb + 2048 + (koffB ^ xorB_sh));
    };

    auto computeTap = [&](int uv) {
        int u = uv / 3, v = uv - u * 3;
        int du = u * PADW + v;
        uint32_t abase[4], axsh[4];
#pragma unroll
        for (int mf = 0; mf < 4; mf++) {
            int q = row_pq[mf] + du;
            abase[mf] = As_u + (uint32_t)q * 128;
            axsh[mf]  = (uint32_t)(q & 7) << 4;
        }
        uint32_t bb = b_base + (uint32_t)((uv & 3) * BBYTES);

        uint32_t bfr[2][8];
        ldB(bfr[0], bb, 0);
        ldB(bfr[1], bb, 1);
#pragma unroll
        for (int kk = 0; kk < 4; kk++) {
            uint32_t koffA = (uint32_t)(kk * 32 + jAh * 16);
            uint32_t* bf = bfr[kk & 1];
            uint32_t afA[4], afB[4];
            ldsm_x4(afA, abase[0] + (koffA ^ axsh[0]));
            ldsm_x4(afB, abase[1] + (koffA ^ axsh[1]));
            mma_fp16(acc[0][0], afA, bf);
            mma_fp16(acc[0][1], afA, bf + 2);
            mma_fp16(acc[0][2], afA, bf + 4);
            mma_fp16(acc[0][3], afA, bf + 6);
            ldsm_x4(afA, abase[2] + (koffA ^ axsh[2]));
            mma_fp16(acc[1][0], afB, bf);
            mma_fp16(acc[1][1], afB, bf + 2);
            mma_fp16(acc[1][2], afB, bf + 4);
            mma_fp16(acc[1][3], afB, bf + 6);
            ldsm_x4(afB, abase[3] + (koffA ^ axsh[3]));
            mma_fp16(acc[2][0], afA, bf);
            mma_fp16(acc[2][1], afA, bf + 2);
            mma_fp16(acc[2][2], afA, bf + 4);
            mma_fp16(acc[2][3], afA, bf + 6);
            mma_fp16(acc[3][0], afB, bf);
            mma_fp16(acc[3][1], afB, bf + 2);
            mma_fp16(acc[3][2], afB, bf + 4);
            mma_fp16(acc[3][3], afB, bf + 6);
            if (kk < 2) ldB(bfr[kk & 1], bb, kk + 2);   // after all users of bf
        }
    };

    for (int cc = 0; cc < 2; cc++) {
        int ccol = cc * 64;
        __syncthreads();

#pragma unroll
        for (int t = 0; t < 10; t++) {
            int c = tid + t * 256;
            if (t < 9 || c < AROWS * 8) {
                int q = c >> 3, j = c & 7;
                cp16(As_u + (uint32_t)(q * 128 + ((j ^ (q & 7)) << 4)),
                     apage + (size_t)q * CI_ + ccol + j * 8);
            }
        }
        stageB(0, ccol);
        stageB(1, ccol);
        CP_COMMIT();

#pragma unroll 1
        for (int w2 = 0; w2 < 9; w2 += 2) {
            CP_WAIT0();
            __syncthreads();
            if (w2 + 2 < 9) {
                stageB(w2 + 2, ccol);
                if (w2 + 3 < 9) stageB(w2 + 3, ccol);
                CP_COMMIT();
            }
#pragma unroll 1
            for (int t = 0; t < 2; t++) {
                int uv = w2 + t;
                if (uv < 9) computeTap(uv);
            }
        }
    }

    // ---- epilogue: direct NCHW stores ----
    float* ob = out + (size_t)b * CO_ * HW;
    int g = lid >> 2, tg = lid & 3;
#pragma unroll
    for (int mf = 0; mf < 4; mf++) {
#pragma unroll
        for (int h = 0; h < 2; h++) {
            int p = p0 + (m_w * 4 + mf) * 16 + g + 8 * h;
            if (p < HW) {
#pragma unroll
                for (int nn = 0; nn < 4; nn++) {
                    int col = n_w * 32 + nn * 8 + (tg << 1);
                    ob[(size_t)col * HW + p]       = acc[mf][nn][2 * h];
                    ob[(size_t)(col + 1) * HW + p] = acc[mf][nn][2 * h + 1];
                }
            }
        }
    }
}

// ---------------------------------------------------------------------------
extern "C" void kernel_launch(void* const* d_in, const int* in_sizes, int n_in,
                              void* d_out, int out_size) {
    const float* input = (const float*)d_in[0];   // [32,128,56,56]
    const float* eps   = (const float*)d_in[1];   // [32,128,128,3,3]
    const float* psi   = (const float*)d_in[2];   // [128,128,3,3]
    const float* mu    = (const float*)d_in[3];   // [128,128,3,3]
    float* out = (float*)d_out;                   // [32,128,56,56]

    prep_all<<<NPREP_TOTAL, 256>>>(input, eps, psi, mu);

    cudaFuncSetAttribute(conv_mma, cudaFuncAttributeMaxDynamicSharedMemorySize, SMEM_CONV);
    conv_mma<<<dim3(NTILES, BB), 256, SMEM_CONV>>>(out);
}